// round 7
// baseline (speedup 1.0000x reference)
#include <cuda_runtime.h>

// 14-qubit, 5-layer variational circuit, batch 2048. One CTA (1024 threads)
// per batch element. State = lane-pair ull arrays Rp/Ip[8192] (128 KB smem):
// each ull packs the two amplitudes differing in canonical qubit 13 (= f32x2
// lanes). 5 in-register rounds per layer (q0-2 with prev ring fused into the
// gather / q3-5 / q6-8 / q9-11 / q12+lane q13), 8 packs per thread. GF(2)
// storage map keeps every round's LDS.64 pattern bank-conflict-free; round E
// is immediate-addressed. Layer 0 closed form; measurement fused in layer 4.

#define NQ 14
#define NL 5
#define NA 6
#define NT 1024

typedef unsigned long long ull;

// ---------- packed f32x2 helpers ----------
__device__ __forceinline__ ull pk(float lo, float hi) {
    ull r; asm("mov.b64 %0, {%1, %2};" : "=l"(r) : "f"(lo), "f"(hi)); return r;
}
__device__ __forceinline__ void upk(ull v, float& lo, float& hi) {
    asm("mov.b64 {%0, %1}, %2;" : "=f"(lo), "=f"(hi) : "l"(v));
}
__device__ __forceinline__ ull f2mul(ull a, ull b) {
    ull d; asm("mul.rn.f32x2 %0, %1, %2;" : "=l"(d) : "l"(a), "l"(b)); return d;
}
__device__ __forceinline__ ull f2fma(ull a, ull b, ull c) {
    ull d; asm("fma.rn.f32x2 %0, %1, %2, %3;" : "=l"(d) : "l"(a), "l"(b), "l"(c)); return d;
}
__device__ __forceinline__ ull swpl(ull v) {
    float a, b; upk(v, a, b); return pk(b, a);
}

struct Gate  { ull ar, ai, br, bi, nai, nbr, nbi; };
struct GateM { ull nai_ai, ai_nai, br_nbr; };

__device__ __forceinline__ void apply2(const Gate& g, ull& a0r, ull& a0i,
                                       ull& a1r, ull& a1i) {
    ull n0r = f2fma(g.br,  a1r, f2fma(g.nbi, a1i, f2fma(g.nai, a0i, f2mul(g.ar,  a0r))));
    ull n0i = f2fma(g.bi,  a1r, f2fma(g.br,  a1i, f2fma(g.ai,  a0r, f2mul(g.ar,  a0i))));
    ull n1r = f2fma(g.ai,  a1i, f2fma(g.ar,  a1r, f2fma(g.nbi, a0i, f2mul(g.nbr, a0r))));
    ull n1i = f2fma(g.nai, a1r, f2fma(g.ar,  a1i, f2fma(g.bi,  a0r, f2mul(g.nbr, a0i))));
    a0r = n0r; a0i = n0i; a1r = n1r; a1i = n1i;
}

// Gate on the SIMD lane bit (canonical qubit 13).
__device__ __forceinline__ void apply_mixed(const Gate& g, const GateM& gm,
                                            ull& Pr, ull& Pi) {
    const ull Qr = swpl(Pr), Qi = swpl(Pi);
    ull Nr = f2fma(g.nbi,     Qi, f2fma(gm.br_nbr, Qr, f2fma(gm.nai_ai, Pi, f2mul(g.ar,      Pr))));
    ull Ni = f2fma(gm.br_nbr, Qi, f2fma(g.bi,      Qr, f2fma(g.ar,      Pi, f2mul(gm.ai_nai, Pr))));
    Pr = Nr; Pi = Ni;
}

// one gate level over 8 packs (pairs differ in pack bit `bit`)
#define LEVEL(g, bit)                                                        \
    {                                                                        \
        _Pragma("unroll")                                                    \
        for (int n = 0; n < 4; ++n) {                                        \
            const int lo = ((n & ~((bit) - 1)) << 1) | (n & ((bit) - 1));    \
            apply2(g, Pr[lo], Pi[lo], Pr[lo | (bit)], Pi[lo | (bit)]);       \
        }                                                                    \
    }

// ---------- GF(2)-linear index maps ----------
__device__ constexpr int ringf14(int x) {
    int y = x;
    y ^= y << 1; y ^= y << 2; y ^= y << 4; y ^= y << 8;
    y &= 0x3FFF;
    return (y & 0x3FFE) | (((y >> 13) ^ x) & 1);
}
__device__ constexpr int ringinv14(int d) {
    int m  = (d ^ (d << 1)) & 0x3FFC;
    int m0 = ((d >> 13) ^ d) & 1;
    int m1 = ((d >> 13) ^ (d >> 1) ^ d) & 1;
    return m | m0 | (m1 << 1);
}
// storage map: a0=q0^q3 a1=q1^q4 a2=q2^q5 a3=q6^q9 a4-6=q3-5 a7=q6
//              a8-9=q7-8 a10-12=q10-12
__device__ constexpr int M13(int q) {
    return ((q ^ (q >> 3)) & 7)
         | ((((q >> 6) ^ (q >> 9)) & 1) << 3)
         | (((q >> 3) & 7) << 4)
         | (((q >> 6) & 1) << 7)
         | (((q >> 7) & 3) << 8)
         | (((q >> 10) & 7) << 10);
}
// per-pack compile-time offsets
__device__ constexpr int OAG(int c) { return M13(ringinv14(c) & 0x1FFF); }
__device__ constexpr int OB (int c) { return M13(c << 3); }   // c | c<<4
__device__ constexpr int OC (int c) { return M13(c << 6); }
__device__ constexpr int OD (int c) { return M13(c << 9); }
__device__ constexpr int RFE(int c) { return ringf14(c << 10); }

__global__ void __launch_bounds__(NT, 1)
qcirc_kernel(const float* __restrict__ x,        // [B, 14]
             const float* __restrict__ iscale,   // [5, 28]
             const float* __restrict__ wts,      // [5, 28]
             const float* __restrict__ ascale,   // [6]
             const float* __restrict__ abias,    // [6]
             float* __restrict__ out)            // [B, 6]
{
    extern __shared__ float2 sm2[];              // [16384] = 128 KB
    float2* R2 = sm2;                            // [8192] re pairs (q13 lanes)
    float2* I2 = sm2 + 8192;                     // [8192] im pairs
    ull* Rp = reinterpret_cast<ull*>(R2);
    ull* Ip = reinterpret_cast<ull*>(I2);

    __shared__ Gate  s_g[NL][NQ];
    __shared__ GateM s_gm[NL];                   // qubit 13 per layer
    __shared__ float s_u0[NQ][4];
    __shared__ float s_red[NT / 32][NA];

    const int t = threadIdx.x;
    const int b = blockIdx.x;

    // ---- fused gate tables: U = RY(beta) RZ(gamma) RY(alpha) -------------
    if (t < NL * NQ) {
        const int l = t / NQ, i = t % NQ;
        const float xi = x[b * NQ + i];
        const float* isl = iscale + l * 2 * NQ;
        const float* wl  = wts    + l * 2 * NQ;
        const float alpha = isl[i] * xi;
        const float gamma = isl[NQ + i] * xi + wl[i];
        const float beta  = wl[NQ + i];
        float sa, ca, sg, cg, sb, cb;
        sincosf(0.5f * alpha, &sa, &ca);
        sincosf(0.5f * gamma, &sg, &cg);
        sincosf(0.5f * beta,  &sb, &cb);
        const float cc = cb * ca, ss = sb * sa;
        const float cs = cb * sa, sc = sb * ca;
        const float ar =  cg * (cc - ss);
        const float ai = -sg * (cc + ss);
        const float br = -cg * (cs + sc);
        const float bi =  sg * (cs - sc);
        Gate gg;
        gg.ar = pk(ar, ar);   gg.ai = pk(ai, ai);
        gg.br = pk(br, br);   gg.bi = pk(bi, bi);
        gg.nai = pk(-ai, -ai); gg.nbr = pk(-br, -br); gg.nbi = pk(-bi, -bi);
        s_g[l][i] = gg;
        if (i == 13) {
            GateM gm;
            gm.nai_ai = pk(-ai, ai);
            gm.ai_nai = pk(ai, -ai);
            gm.br_nbr = pk(br, -br);
            s_gm[l] = gm;
        }
        if (l == 0) {
            s_u0[i][0] = ar; s_u0[i][1] = ai; s_u0[i][2] = br; s_u0[i][3] = bi;
        }
    }
    __syncthreads();

    // ---- per-thread bases (GF(2)-linear in t) -----------------------------
    const int gA = M13(ringinv14(t << 3) & 0x1FFF);            // A gather
    const int t9 = (t >> 9) & 1;                               // A lane select
    const int sA = M13(t << 3);                                // A scatter
    const int bB = M13((t & 7) | (((t >> 3) & 0x7F) << 6));
    const int bC = M13((t & 7) | (((t >> 4) & 7) << 3)
                       | (((t >> 3) & 1) << 9) | (((t >> 7) & 7) << 10));
    const int bD = M13((t & 7) | (((t >> 4) & 7) << 3) | (((t >> 3) & 1) << 6)
                       | (((t >> 7) & 3) << 7) | (((t >> 9) & 1) << 12));
    const int qE = (t & 7) | (((t >> 4) & 7) << 3)
                 | (((t >> 3) & 1) << 6) | (((t >> 7) & 7) << 7);
    const int bE  = M13(qE);
    const int rfE = ringf14(qE);                               // measurement

    // ---- layer 0: pre-ring product state, closed form ---------------------
    {
        // distributed qubits per round-E map: t-bit j -> qubit Qmap[j]
        const int Qmap[10] = {0, 1, 2, 6, 3, 4, 5, 7, 8, 9};
        float Pr0 = 1.0f, Pi0 = 0.0f;
        #pragma unroll
        for (int j = 0; j < 10; ++j) {
            const int q = Qmap[j];
            const int bq = (t >> j) & 1;
            const float fr = bq ? -s_u0[q][2] : s_u0[q][0];
            const float fi = bq ?  s_u0[q][3] : s_u0[q][1];
            const float nr = Pr0 * fr - Pi0 * fi;
            Pi0 = Pr0 * fi + Pi0 * fr;
            Pr0 = nr;
        }
        float cr[8], ci[8];
        cr[0] = Pr0; ci[0] = Pi0;
        #pragma unroll
        for (int e = 0; e < 3; ++e) {          // pack bits -> qubits 10,11,12
            const int q = 10 + e;
            const float a0r = s_u0[q][0], a0i = s_u0[q][1];
            const float f1r = -s_u0[q][2], f1i = s_u0[q][3];
            #pragma unroll
            for (int c = 0; c < (1 << e); ++c) {
                const float tr = cr[c], ti = ci[c];
                cr[c] = tr * a0r - ti * a0i;
                ci[c] = tr * a0i + ti * a0r;
                cr[c | (1 << e)] = tr * f1r - ti * f1i;
                ci[c | (1 << e)] = tr * f1i + ti * f1r;
            }
        }
        const float g0r = s_u0[13][0], g0i = s_u0[13][1];     // lane factors
        const float g1r = -s_u0[13][2], g1i = s_u0[13][3];
        #pragma unroll
        for (int c = 0; c < 8; ++c) {
            const int a = bE + (c << 10);
            Rp[a] = pk(cr[c] * g0r - ci[c] * g0i, cr[c] * g1r - ci[c] * g1i);
            Ip[a] = pk(cr[c] * g0i + ci[c] * g0r, cr[c] * g1i + ci[c] * g1r);
        }
    }
    __syncthreads();

    float acc[NA];
    #pragma unroll
    for (int a = 0; a < NA; ++a) acc[a] = 0.0f;

    ull Pr[8], Pi[8];
    #pragma unroll 1
    for (int l = 1; l < NL; ++l) {
        // ===== round A: qubits 0..2, previous layer's ring fused ==========
        #pragma unroll
        for (int c = 0; c < 8; ++c) {
            const int s = gA ^ OAG(c);
            const float2 r0 = R2[s], r1 = R2[s ^ 3];
            const float2 i0 = I2[s], i1 = I2[s ^ 3];
            Pr[c] = t9 ? pk(r0.y, r1.x) : pk(r0.x, r1.y);
            Pi[c] = t9 ? pk(i0.y, i1.x) : pk(i0.x, i1.y);
        }
        LEVEL(s_g[l][0], 1)
        LEVEL(s_g[l][1], 2)
        LEVEL(s_g[l][2], 4)
        __syncthreads();                 // all gathers done before any write
        #pragma unroll
        for (int c = 0; c < 8; ++c) {
            const int a = sA ^ c;
            Rp[a] = Pr[c]; Ip[a] = Pi[c];
        }
        __syncthreads();

        // ===== round B: qubits 3..5 (in-place) ============================
        #pragma unroll
        for (int c = 0; c < 8; ++c) {
            const int a = bB ^ OB(c);
            Pr[c] = Rp[a]; Pi[c] = Ip[a];
        }
        LEVEL(s_g[l][3], 1)
        LEVEL(s_g[l][4], 2)
        LEVEL(s_g[l][5], 4)
        #pragma unroll
        for (int c = 0; c < 8; ++c) {
            const int a = bB ^ OB(c);
            Rp[a] = Pr[c]; Ip[a] = Pi[c];
        }
        __syncthreads();

        // ===== round C: qubits 6..8 (in-place) ============================
        #pragma unroll
        for (int c = 0; c < 8; ++c) {
            const int a = bC ^ OC(c);
            Pr[c] = Rp[a]; Pi[c] = Ip[a];
        }
        LEVEL(s_g[l][6], 1)
        LEVEL(s_g[l][7], 2)
        LEVEL(s_g[l][8], 4)
        #pragma unroll
        for (int c = 0; c < 8; ++c) {
            const int a = bC ^ OC(c);
            Rp[a] = Pr[c]; Ip[a] = Pi[c];
        }
        __syncthreads();

        // ===== round D: qubits 9..11 (in-place) ===========================
        #pragma unroll
        for (int c = 0; c < 8; ++c) {
            const int a = bD ^ OD(c);
            Pr[c] = Rp[a]; Pi[c] = Ip[a];
        }
        LEVEL(s_g[l][9],  1)
        LEVEL(s_g[l][10], 2)
        LEVEL(s_g[l][11], 4)
        #pragma unroll
        for (int c = 0; c < 8; ++c) {
            const int a = bD ^ OD(c);
            Rp[a] = Pr[c]; Ip[a] = Pi[c];
        }
        __syncthreads();

        // ===== round E: qubit 12 (pack bit 2) + qubit 13 (lane), in-place =
        #pragma unroll
        for (int c = 0; c < 8; ++c) {
            const int a = bE + (c << 10);            // immediate addressing
            Pr[c] = Rp[a]; Pi[c] = Ip[a];
        }
        LEVEL(s_g[l][12], 4)
        {
            const Gate g = s_g[l][13];
            const GateM gm = s_gm[l];
            #pragma unroll
            for (int c = 0; c < 8; ++c) apply_mixed(g, gm, Pr[c], Pi[c]);
        }
        if (l < NL - 1) {
            #pragma unroll
            for (int c = 0; c < 8; ++c) {
                const int a = bE + (c << 10);
                Rp[a] = Pr[c]; Ip[a] = Pi[c];
            }
            __syncthreads();
        } else {
            // ---- measurement fused with the final (owed) ring ------------
            // lane1 ring-index = lane0 ^ ringf(1<<13) = ^0x2001:
            // only Z_0 differs between lanes.
            #pragma unroll
            for (int c = 0; c < 8; ++c) {
                const ull Pp = f2fma(Pi[c], Pi[c], f2mul(Pr[c], Pr[c]));
                float p0, p1;
                upk(Pp, p0, p1);
                const int d0 = rfE ^ RFE(c);
                const float sum = p0 + p1, dif = p0 - p1;
                acc[0] += (d0 & 1) ? -dif : dif;
                #pragma unroll
                for (int a = 1; a < NA; ++a)
                    acc[a] += ((d0 >> a) & 1) ? -sum : sum;
            }
        }
    }

    // ---- block reduction of <Z_a> ----------------------------------------
    #pragma unroll
    for (int a = 0; a < NA; ++a) {
        #pragma unroll
        for (int off = 16; off; off >>= 1)
            acc[a] += __shfl_xor_sync(0xffffffffu, acc[a], off);
    }
    const int lane = t & 31, warp = t >> 5;
    if (lane == 0) {
        #pragma unroll
        for (int a = 0; a < NA; ++a) s_red[warp][a] = acc[a];
    }
    __syncthreads();
    if (t < NA) {
        float s = 0.0f;
        #pragma unroll
        for (int w = 0; w < NT / 32; ++w) s += s_red[w][t];
        out[b * NA + t] = s * ascale[t] + abias[t];
    }
}

extern "C" void kernel_launch(void* const* d_in, const int* in_sizes, int n_in,
                              void* d_out, int out_size) {
    const float* x      = (const float*)d_in[0];
    const float* iscale = (const float*)d_in[1];
    const float* wts    = (const float*)d_in[2];
    const float* ascale = (const float*)d_in[3];
    const float* abias  = (const float*)d_in[4];
    float* out = (float*)d_out;
    const int B = in_sizes[0] / NQ;

    const size_t shmem = (size_t)16384 * sizeof(float2);   // 128 KB
    cudaFuncSetAttribute(qcirc_kernel,
                         cudaFuncAttributeMaxDynamicSharedMemorySize,
                         (int)shmem);
    qcirc_kernel<<<B, NT, shmem>>>(x, iscale, wts, ascale, abias, out);
}

// round 8
// speedup vs baseline: 1.1308x; 1.1308x over previous
#include <cuda_runtime.h>

// 14-qubit, 5-layer variational circuit, batch 2048. One CTA (512 threads)
// per batch element. State = lane-pair ull arrays Rp/Ip[8192] (128 KB smem):
// each ull packs the two amplitudes differing in canonical qubit 13 (f32x2
// lanes). 3 smem rounds per layer: A (ring-fused gather, gates q0-3 + mixed
// lane gate q13), B (q4-7, in place), C (q8-11 in place + q12 via shfl_xor
// across lane bit t4). Storage map M(q)=q^(((q>>4)^(q>>8))&15) makes every
// round's LDS.64/STS.64 pattern bank-conflict-free (GF(2)-verified).
// Layer 0 closed form; measurement fused into layer 4's round C.

#define NQ 14
#define NL 5
#define NA 6
#define NT 512

typedef unsigned long long ull;

// ---------- packed f32x2 helpers ----------
__device__ __forceinline__ ull pk(float lo, float hi) {
    ull r; asm("mov.b64 %0, {%1, %2};" : "=l"(r) : "f"(lo), "f"(hi)); return r;
}
__device__ __forceinline__ void upk(ull v, float& lo, float& hi) {
    asm("mov.b64 {%0, %1}, %2;" : "=f"(lo), "=f"(hi) : "l"(v));
}
__device__ __forceinline__ ull f2mul(ull a, ull b) {
    ull d; asm("mul.rn.f32x2 %0, %1, %2;" : "=l"(d) : "l"(a), "l"(b)); return d;
}
__device__ __forceinline__ ull f2fma(ull a, ull b, ull c) {
    ull d; asm("fma.rn.f32x2 %0, %1, %2, %3;" : "=l"(d) : "l"(a), "l"(b), "l"(c)); return d;
}
__device__ __forceinline__ ull swpl(ull v) {
    float a, b; upk(v, a, b); return pk(b, a);
}

struct Gate  { ull ar, ai, br, bi, nai, nbr, nbi; };
struct GateM { ull nai_ai, ai_nai, br_nbr; };

__device__ __forceinline__ void apply2(const Gate& g, ull& a0r, ull& a0i,
                                       ull& a1r, ull& a1i) {
    ull n0r = f2fma(g.br,  a1r, f2fma(g.nbi, a1i, f2fma(g.nai, a0i, f2mul(g.ar,  a0r))));
    ull n0i = f2fma(g.bi,  a1r, f2fma(g.br,  a1i, f2fma(g.ai,  a0r, f2mul(g.ar,  a0i))));
    ull n1r = f2fma(g.ai,  a1i, f2fma(g.ar,  a1r, f2fma(g.nbi, a0i, f2mul(g.nbr, a0r))));
    ull n1i = f2fma(g.nai, a1r, f2fma(g.ar,  a1i, f2fma(g.bi,  a0r, f2mul(g.nbr, a0i))));
    a0r = n0r; a0i = n0i; a1r = n1r; a1i = n1i;
}

// Gate on the SIMD lane bit (canonical qubit 13).
__device__ __forceinline__ void apply_mixed(const Gate& g, const GateM& gm,
                                            ull& Pr, ull& Pi) {
    const ull Qr = swpl(Pr), Qi = swpl(Pi);
    ull Nr = f2fma(g.nbi,     Qi, f2fma(gm.br_nbr, Qr, f2fma(gm.nai_ai, Pi, f2mul(g.ar,      Pr))));
    ull Ni = f2fma(gm.br_nbr, Qi, f2fma(g.bi,      Qr, f2fma(g.ar,      Pi, f2mul(gm.ai_nai, Pr))));
    Pr = Nr; Pi = Ni;
}

// one gate level over 16 packs (pairs differ in pack bit `bit`)
#define LEVEL(g, bit)                                                        \
    {                                                                        \
        _Pragma("unroll")                                                    \
        for (int n = 0; n < 8; ++n) {                                        \
            const int lo = ((n & ~((bit) - 1)) << 1) | (n & ((bit) - 1));    \
            apply2(g, Pr[lo], Pi[lo], Pr[lo | (bit)], Pi[lo | (bit)]);       \
        }                                                                    \
    }

// ---------- GF(2)-linear index maps ----------
__device__ constexpr int ringf14(int x) {
    int y = x;
    y ^= y << 1; y ^= y << 2; y ^= y << 4; y ^= y << 8;
    y &= 0x3FFF;
    return (y & 0x3FFE) | (((y >> 13) ^ x) & 1);
}
__device__ constexpr int ringinv14(int d) {
    int m  = (d ^ (d << 1)) & 0x3FFC;
    int m0 = ((d >> 13) ^ d) & 1;
    int m1 = ((d >> 13) ^ (d >> 1) ^ d) & 1;
    return m | m0 | (m1 << 1);
}
// storage map: a0-3 = q0-3 ^ q4-7 ^ q8-11, a4-12 = q4-12
__device__ constexpr int M13(int q) { return q ^ (((q >> 4) ^ (q >> 8)) & 15); }
// compile-time per-pack offsets
__device__ constexpr int OA(int c) { return M13(ringinv14(c) & 0x1FFF); }
__device__ constexpr int OB(int c) { return M13(c << 4); }
__device__ constexpr int OC(int c) { return M13(c << 8); }
__device__ constexpr int PAR4(int c) { return (0x6996 >> c) & 1; }  // nibble parity

__global__ void __launch_bounds__(NT, 1)
qcirc_kernel(const float* __restrict__ x,        // [B, 14]
             const float* __restrict__ iscale,   // [5, 28]
             const float* __restrict__ wts,      // [5, 28]
             const float* __restrict__ ascale,   // [6]
             const float* __restrict__ abias,    // [6]
             float* __restrict__ out)            // [B, 6]
{
    extern __shared__ float2 sm2[];              // [16384] = 128 KB
    float2* R2 = sm2;                            // [8192] re pairs (q13 lanes)
    float2* I2 = sm2 + 8192;                     // [8192] im pairs
    ull* Rp = reinterpret_cast<ull*>(R2);
    ull* Ip = reinterpret_cast<ull*>(I2);

    __shared__ Gate  s_g[NL][NQ];
    __shared__ GateM s_gm[NL];                   // qubit 13 per layer
    __shared__ float s_u0[NQ][4];
    __shared__ float s_red[NT / 32][NA];

    const int t = threadIdx.x;
    const int b = blockIdx.x;

    // ---- fused gate tables: U = RY(beta) RZ(gamma) RY(alpha) --------------
    if (t < NL * NQ) {
        const int l = t / NQ, i = t % NQ;
        const float xi = x[b * NQ + i];
        const float* isl = iscale + l * 2 * NQ;
        const float* wl  = wts    + l * 2 * NQ;
        const float alpha = isl[i] * xi;
        const float gamma = isl[NQ + i] * xi + wl[i];
        const float beta  = wl[NQ + i];
        float sa, ca, sg, cg, sb, cb;
        sincosf(0.5f * alpha, &sa, &ca);
        sincosf(0.5f * gamma, &sg, &cg);
        sincosf(0.5f * beta,  &sb, &cb);
        const float cc = cb * ca, ss = sb * sa;
        const float cs = cb * sa, sc = sb * ca;
        const float ar =  cg * (cc - ss);
        const float ai = -sg * (cc + ss);
        const float br = -cg * (cs + sc);
        const float bi =  sg * (cs - sc);
        Gate gg;
        gg.ar = pk(ar, ar);   gg.ai = pk(ai, ai);
        gg.br = pk(br, br);   gg.bi = pk(bi, bi);
        gg.nai = pk(-ai, -ai); gg.nbr = pk(-br, -br); gg.nbi = pk(-bi, -bi);
        s_g[l][i] = gg;
        if (i == 13) {
            GateM gm;
            gm.nai_ai = pk(-ai, ai);
            gm.ai_nai = pk(ai, -ai);
            gm.br_nbr = pk(br, -br);
            s_gm[l] = gm;
        }
        if (l == 0) {
            s_u0[i][0] = ar; s_u0[i][1] = ai; s_u0[i][2] = br; s_u0[i][3] = bi;
        }
    }
    __syncthreads();

    // ---- per-thread bases --------------------------------------------------
    // round A thread assignment: j4=t0 j9=t1 j6=t2 j11=t3 j5=t4 j7=t5 j8=t6
    //                            j10=t7 j12=t8  (chosen for gather invertibility)
    const int TAv = ((t & 1) << 4)        | (((t >> 1) & 1) << 9)
                  | (((t >> 2) & 1) << 6) | (((t >> 3) & 1) << 11)
                  | (((t >> 4) & 1) << 5) | (((t >> 5) & 1) << 7)
                  | (((t >> 6) & 1) << 8) | (((t >> 7) & 1) << 10)
                  | (((t >> 8) & 1) << 12);
    const int gA   = M13(ringinv14(TAv) & 0x1FFF);     // A gather base
    const int selA = (t >> 8) & 1;                     // A lane select
    const int sA   = M13(TAv);                         // A scatter base
    // round B: q0-3=t0-3, q4-7=c, q8-12=t4-8
    const int bB   = M13((t & 15) | (((t >> 4) & 31) << 8));
    // round C: q0-3=t0-3, q12=t4 (shfl lane bit), q4-7=t5-8, q8-11=c
    const int qC   = (t & 15) | (((t >> 4) & 1) << 12) | (((t >> 5) & 15) << 4);
    const int bC   = M13(qC);
    const int rfC  = ringf14(qC);                      // measurement signs
    const int q12b = (t >> 4) & 1;                     // shfl-gate role

    // ---- layer 0: pre-ring product state, closed form ----------------------
    {
        const int Qmap[9] = {0, 1, 2, 3, 8, 9, 10, 11, 12};
        float Pr0 = 1.0f, Pi0 = 0.0f;
        #pragma unroll
        for (int j = 0; j < 9; ++j) {
            const int q = Qmap[j];
            const int bq = (t >> j) & 1;
            const float fr = bq ? -s_u0[q][2] : s_u0[q][0];
            const float fi = bq ?  s_u0[q][3] : s_u0[q][1];
            const float nr = Pr0 * fr - Pi0 * fi;
            Pi0 = Pr0 * fi + Pi0 * fr;
            Pr0 = nr;
        }
        float cr[16], ci[16];
        cr[0] = Pr0; ci[0] = Pi0;
        #pragma unroll
        for (int e = 0; e < 4; ++e) {                  // pack bit e -> qubit 4+e
            const int q = 4 + e;
            const float a0r = s_u0[q][0], a0i = s_u0[q][1];
            const float f1r = -s_u0[q][2], f1i = s_u0[q][3];
            #pragma unroll
            for (int c = 0; c < (1 << e); ++c) {
                const float tr = cr[c], ti = ci[c];
                cr[c] = tr * a0r - ti * a0i;
                ci[c] = tr * a0i + ti * a0r;
                cr[c | (1 << e)] = tr * f1r - ti * f1i;
                ci[c | (1 << e)] = tr * f1i + ti * f1r;
            }
        }
        const float g0r = s_u0[13][0], g0i = s_u0[13][1];   // q13 lane factors
        const float g1r = -s_u0[13][2], g1i = s_u0[13][3];
        #pragma unroll
        for (int c = 0; c < 16; ++c) {
            const int a = bB ^ OB(c);
            Rp[a] = pk(cr[c] * g0r - ci[c] * g0i, cr[c] * g1r - ci[c] * g1i);
            Ip[a] = pk(cr[c] * g0i + ci[c] * g0r, cr[c] * g1i + ci[c] * g1r);
        }
    }
    __syncthreads();

    float accS = 0.0f, acc0 = 0.0f;
    ull Pr[16], Pi[16];
    #pragma unroll 1
    for (int l = 1; l < NL; ++l) {
        // ===== round A: qubits 0..3 + lane q13; prev ring fused in gather ==
        if (selA == 0) {
            #pragma unroll
            for (int c = 0; c < 16; ++c) {
                const int a = gA ^ OA(c);
                const float2 r0 = R2[a], r1 = R2[a ^ 3];
                const float2 i0 = I2[a], i1 = I2[a ^ 3];
                Pr[c] = pk(r0.x, r1.y); Pi[c] = pk(i0.x, i1.y);
            }
        } else {
            #pragma unroll
            for (int c = 0; c < 16; ++c) {
                const int a = gA ^ OA(c);
                const float2 r0 = R2[a], r1 = R2[a ^ 3];
                const float2 i0 = I2[a], i1 = I2[a ^ 3];
                Pr[c] = pk(r0.y, r1.x); Pi[c] = pk(i0.y, i1.x);
            }
        }
        LEVEL(s_g[l][0], 1)
        LEVEL(s_g[l][1], 2)
        LEVEL(s_g[l][2], 4)
        LEVEL(s_g[l][3], 8)
        {
            const Gate g = s_g[l][13];
            const GateM gm = s_gm[l];
            #pragma unroll
            for (int c = 0; c < 16; ++c) apply_mixed(g, gm, Pr[c], Pi[c]);
        }
        __syncthreads();                          // all gathers before writes
        #pragma unroll
        for (int c = 0; c < 16; ++c) {
            const int a = sA ^ c;                 // M13(c)=c for c<16
            Rp[a] = Pr[c]; Ip[a] = Pi[c];
        }
        __syncthreads();

        // ===== round B: qubits 4..7 (in place) =============================
        #pragma unroll
        for (int c = 0; c < 16; ++c) {
            const int a = bB ^ OB(c);
            Pr[c] = Rp[a]; Pi[c] = Ip[a];
        }
        LEVEL(s_g[l][4], 1)
        LEVEL(s_g[l][5], 2)
        LEVEL(s_g[l][6], 4)
        LEVEL(s_g[l][7], 8)
        #pragma unroll
        for (int c = 0; c < 16; ++c) {
            const int a = bB ^ OB(c);
            Rp[a] = Pr[c]; Ip[a] = Pi[c];
        }
        __syncthreads();

        // ===== round C: qubits 8..11 (packs) + q12 (shfl), in place ========
        #pragma unroll
        for (int c = 0; c < 16; ++c) {
            const int a = bC ^ OC(c);
            Pr[c] = Rp[a]; Pi[c] = Ip[a];
        }
        LEVEL(s_g[l][8],  1)
        LEVEL(s_g[l][9],  2)
        LEVEL(s_g[l][10], 4)
        LEVEL(s_g[l][11], 8)
        {
            // q12 gate: butterfly across warp-lane bit t4 via shfl_xor(16).
            // role bit0: n = a*m + b*p ; bit1: n = conj(a)*m - conj(b)*p
            const Gate g = s_g[l][12];
            const ull mycr  = g.ar;
            const ull myci  = q12b ? g.nai : g.ai;
            const ull nmyci = q12b ? g.ai  : g.nai;
            const ull pcr   = q12b ? g.nbr : g.br;
            const ull pci   = g.bi;
            const ull npci  = g.nbi;
            #pragma unroll
            for (int c = 0; c < 16; ++c) {
                const ull pR = __shfl_xor_sync(0xffffffffu, Pr[c], 16);
                const ull pI = __shfl_xor_sync(0xffffffffu, Pi[c], 16);
                const ull nr = f2fma(npci, pI, f2fma(pcr, pR,
                               f2fma(nmyci, Pi[c], f2mul(mycr, Pr[c]))));
                const ull ni = f2fma(pci,  pR, f2fma(pcr, pI,
                               f2fma(myci,  Pr[c], f2mul(mycr, Pi[c]))));
                Pr[c] = nr; Pi[c] = ni;
            }
        }
        if (l < NL - 1) {
            #pragma unroll
            for (int c = 0; c < 16; ++c) {
                const int a = bC ^ OC(c);
                Rp[a] = Pr[c]; Ip[a] = Pi[c];
            }
            __syncthreads();
        } else {
            // ---- measurement fused with the final (owed) ring ------------
            // d = ringf(p): d1..d5 are per-thread (bits of rfC); d0 flips
            // with pack parity (p8-11 = c) and with lane p13.
            const int D0t = rfC & 1;
            #pragma unroll
            for (int c = 0; c < 16; ++c) {
                const ull Pp = f2fma(Pi[c], Pi[c], f2mul(Pr[c], Pr[c]));
                float p0, p1;
                upk(Pp, p0, p1);
                accS += p0 + p1;
                const float d = p0 - p1;
                acc0 += ((D0t ^ PAR4(c)) & 1) ? -d : d;
            }
        }
    }

    // ---- per-thread signs, then block reduction of <Z_a> ------------------
    float acc[NA];
    acc[0] = acc0;
    #pragma unroll
    for (int a = 1; a < NA; ++a)
        acc[a] = ((rfC >> a) & 1) ? -accS : accS;

    #pragma unroll
    for (int a = 0; a < NA; ++a) {
        #pragma unroll
        for (int off = 16; off; off >>= 1)
            acc[a] += __shfl_xor_sync(0xffffffffu, acc[a], off);
    }
    const int lane = t & 31, warp = t >> 5;
    if (lane == 0) {
        #pragma unroll
        for (int a = 0; a < NA; ++a) s_red[warp][a] = acc[a];
    }
    __syncthreads();
    if (t < NA) {
        float s = 0.0f;
        #pragma unroll
        for (int w = 0; w < NT / 32; ++w) s += s_red[w][t];
        out[b * NA + t] = s * ascale[t] + abias[t];
    }
}

extern "C" void kernel_launch(void* const* d_in, const int* in_sizes, int n_in,
                              void* d_out, int out_size) {
    const float* x      = (const float*)d_in[0];
    const float* iscale = (const float*)d_in[1];
    const float* wts    = (const float*)d_in[2];
    const float* ascale = (const float*)d_in[3];
    const float* abias  = (const float*)d_in[4];
    float* out = (float*)d_out;
    const int B = in_sizes[0] / NQ;

    const size_t shmem = (size_t)16384 * sizeof(float2);   // 128 KB
    cudaFuncSetAttribute(qcirc_kernel,
                         cudaFuncAttributeMaxDynamicSharedMemorySize,
                         (int)shmem);
    qcirc_kernel<<<B, NT, shmem>>>(x, iscale, wts, ascale, abias, out);
}